// round 1
// baseline (speedup 1.0000x reference)
#include <cuda_runtime.h>
#include <cuda_bf16.h>

// Device-global scratch (no allocations allowed).
// g_abg[r]   = (a_r, b_r, c_r, unused) where exp2(a*d^2 + b*d + c) == exp(coeff_r*(d-off_r)^2)
// g_prefz[(b*MAXZ+v)*R + r] = prefactor for batch b, atom-type v, radial r
__device__ float4 g_abg[128];
__device__ float  g_prefz[2 * 128 * 64];   // generous: B*MAXZ*R up to 16384

// ---------------------------------------------------------------------------
// Kernel 1: fold radial RBF params into quadratic-in-d exp2 coefficients.
// ---------------------------------------------------------------------------
__global__ void prep_abg_kernel(const float* __restrict__ r_off,
                                const float* __restrict__ r_wid, int R) {
    int r = threadIdx.x;
    if (r < R) {
        float o = r_off[r];
        float w = r_wid[r];
        const float LOG2E = 1.4426950408889634f;
        float c = (-0.5f / (w * w)) * LOG2E;   // pre-scaled for exp2
        g_abg[r] = make_float4(c, -2.0f * c * o, c * o * o, 0.0f);
    }
}

// ---------------------------------------------------------------------------
// Kernel 2: prefactor per (batch, atom-type).
//   pref[b,v,r] = sum_a emb[v,a] * exp(-0.5/tw_a^2 * (t_b - to_a)^2) * W[a,r]
// grid = B*MAXZ blocks, 128 threads.
// ---------------------------------------------------------------------------
__global__ void prep_pref_kernel(const float* __restrict__ t,
                                 const float* __restrict__ emb,
                                 const float* __restrict__ W,
                                 const float* __restrict__ t_off,
                                 const float* __restrict__ t_wid,
                                 int A, int R, int MAXZ) {
    __shared__ float sx[256];
    int b = blockIdx.x / MAXZ;
    int v = blockIdx.x % MAXZ;
    int a = threadIdx.x;
    if (a < A) {
        float tw = t_wid[a];
        float dt = t[b] - t_off[a];
        float c  = -0.5f / (tw * tw);
        sx[a] = emb[(size_t)v * A + a] * __expf(c * dt * dt);
    }
    __syncthreads();
    int r = threadIdx.x;
    if (r < R) {
        float s = 0.0f;
        for (int aa = 0; aa < A; aa++)
            s = fmaf(sx[aa], W[(size_t)aa * R + r], s);
        g_prefz[((size_t)b * MAXZ + v) * R + r] = s;
    }
}

// ---------------------------------------------------------------------------
// Kernel 3: main pairwise kernel. One block per (b, i).
// smem: [N] float4 positions of batch b, then [R] float4 packed (a,b,c,pref).
// Each thread strides over j, 50-way unrolled radial loop:
//   phi += pref_r * exp2(a_r*d2 + b_r*d + c_r)
// Diagonal j==i is harmless: r_ij = 0 => contributes exactly 0.
// ---------------------------------------------------------------------------
template <int RR>
__global__ __launch_bounds__(256)
void vf_main_kernel(const float* __restrict__ pos,
                    const int*   __restrict__ z,
                    float*       __restrict__ out,
                    int N, int R, int MAXZ) {
    extern __shared__ float4 smem[];
    float4* s_pos  = smem;        // [N]
    float4* s_pack = smem + N;    // [R]
    __shared__ float s_red[3 * 8];

    int bi = blockIdx.x;
    int b  = bi / N;
    int i  = bi % N;

    const float* posb = pos + (size_t)b * N * 3;
    for (int idx = threadIdx.x; idx < N; idx += blockDim.x) {
        s_pos[idx] = make_float4(posb[idx * 3 + 0],
                                 posb[idx * 3 + 1],
                                 posb[idx * 3 + 2], 0.0f);
    }
    int Ruse = (RR > 0) ? RR : R;
    if (threadIdx.x < Ruse) {
        float4 p = g_abg[threadIdx.x];
        p.w = g_prefz[((size_t)b * MAXZ + z[i]) * R + threadIdx.x];
        s_pack[threadIdx.x] = p;
    }
    __syncthreads();

    float4 pi = s_pos[i];
    float a0 = 0.0f, a1 = 0.0f, a2 = 0.0f;

    for (int j = threadIdx.x; j < N; j += blockDim.x) {
        float4 pj = s_pos[j];
        float rx = pi.x - pj.x;
        float ry = pi.y - pj.y;
        float rz = pi.z - pj.z;
        float d2 = fmaf(rx, rx, fmaf(ry, ry, rz * rz)) + 1e-6f;
        float d  = sqrtf(d2);
        float phi = 0.0f;
        if (RR > 0) {
#pragma unroll
            for (int r = 0; r < RR; r++) {
                float4 p = s_pack[r];
                float arg = fmaf(p.x, d2, fmaf(p.y, d, p.z));
                phi = fmaf(p.w, exp2f(arg), phi);
            }
        } else {
            for (int r = 0; r < R; r++) {
                float4 p = s_pack[r];
                float arg = fmaf(p.x, d2, fmaf(p.y, d, p.z));
                phi = fmaf(p.w, exp2f(arg), phi);
            }
        }
        a0 = fmaf(phi, rx, a0);
        a1 = fmaf(phi, ry, a1);
        a2 = fmaf(phi, rz, a2);
    }

    // warp reduction
#pragma unroll
    for (int off = 16; off > 0; off >>= 1) {
        a0 += __shfl_down_sync(0xFFFFFFFFu, a0, off);
        a1 += __shfl_down_sync(0xFFFFFFFFu, a1, off);
        a2 += __shfl_down_sync(0xFFFFFFFFu, a2, off);
    }
    int warp = threadIdx.x >> 5;
    int lane = threadIdx.x & 31;
    if (lane == 0) {
        s_red[warp * 3 + 0] = a0;
        s_red[warp * 3 + 1] = a1;
        s_red[warp * 3 + 2] = a2;
    }
    __syncthreads();
    if (threadIdx.x == 0) {
        float s0 = 0.0f, s1 = 0.0f, s2 = 0.0f;
        int nw = blockDim.x >> 5;
        for (int w = 0; w < nw; w++) {
            s0 += s_red[w * 3 + 0];
            s1 += s_red[w * 3 + 1];
            s2 += s_red[w * 3 + 2];
        }
        out[(size_t)bi * 3 + 0] = s0 + pi.x;
        out[(size_t)bi * 3 + 1] = s1 + pi.y;
        out[(size_t)bi * 3 + 2] = s2 + pi.z;
    }
}

// ---------------------------------------------------------------------------
// Launch wrapper. Inputs per metadata order:
//  0 positions [B,N,3] f32, 1 t [B] f32, 2 z [N] i32, 3 emb [MAXZ,A] f32,
//  4 W [A,R] f32, 5 rad_off [R], 6 rad_wid [R], 7 time_off [A], 8 time_wid [A]
// ---------------------------------------------------------------------------
extern "C" void kernel_launch(void* const* d_in, const int* in_sizes, int n_in,
                              void* d_out, int out_size) {
    const float* positions = (const float*)d_in[0];
    const float* t         = (const float*)d_in[1];
    const int*   z         = (const int*)  d_in[2];
    const float* emb       = (const float*)d_in[3];
    const float* W         = (const float*)d_in[4];
    const float* r_off     = (const float*)d_in[5];
    const float* r_wid     = (const float*)d_in[6];
    const float* t_off     = (const float*)d_in[7];
    const float* t_wid     = (const float*)d_in[8];

    int B    = in_sizes[1];
    int N    = in_sizes[2];
    int R    = in_sizes[5];
    int A    = in_sizes[7];
    int MAXZ = in_sizes[3] / A;

    prep_abg_kernel<<<1, 128>>>(r_off, r_wid, R);
    prep_pref_kernel<<<B * MAXZ, 128>>>(t, emb, W, t_off, t_wid, A, R, MAXZ);

    size_t smem = (size_t)(N + R) * sizeof(float4);
    float* out = (float*)d_out;
    if (R == 50) {
        vf_main_kernel<50><<<B * N, 256, smem>>>(positions, z, out, N, R, MAXZ);
    } else {
        vf_main_kernel<0><<<B * N, 256, smem>>>(positions, z, out, N, R, MAXZ);
    }
}

// round 2
// speedup vs baseline: 2.2671x; 2.2671x over previous
#include <cuda_runtime.h>
#include <cuda_bf16.h>

// ---------------------------------------------------------------------------
// Piecewise-quadratic table of phi(d) per (batch, atom-type).
//   phi_{b,v}(d) = sum_r pref_r[b,v] * exp(-0.5/w_r^2 * (d - o_r)^2)
// Table: K intervals over d in [0, DMAX]; entry k = (a, b, c, pad) with
//   phi(d) ~= a + b*u + c*u^2,  u = d - k*h
// fitted through endpoint/midpoint/endpoint samples of the interval.
// ---------------------------------------------------------------------------
#define KNOTS   1024
#define DMAXF   16.0f
#define SLICES  8
#define KS      (KNOTS / SLICES)   // intervals per build block: 128

__device__ float4 g_table[2 * 128 * KNOTS];   // up to B=2, MAXZ=128

__device__ __forceinline__ float ex2f_fast(float x) {
    float y;
    asm("ex2.approx.ftz.f32 %0, %1;" : "=f"(y) : "f"(x));
    return y;
}
__device__ __forceinline__ float sqrtf_fast(float x) {
    float y;
    asm("sqrt.approx.f32 %0, %1;" : "=f"(y) : "f"(x));
    return y;
}

// ---------------------------------------------------------------------------
// Kernel 1: build tables. grid = (B*MAXZ) * SLICES blocks, 256 threads.
// Each block: compute pref[r] for its (b,v), sample phi at 2*KS+1 points in
// its d-slice, fit per-interval quadratics, write KS float4 entries.
// ---------------------------------------------------------------------------
__global__ __launch_bounds__(256)
void build_table_kernel(const float* __restrict__ t,
                        const float* __restrict__ emb,
                        const float* __restrict__ W,
                        const float* __restrict__ r_off,
                        const float* __restrict__ r_wid,
                        const float* __restrict__ t_off,
                        const float* __restrict__ t_wid,
                        int A, int R, int MAXZ) {
    __shared__ float sx[128];       // emb[v,a] * time-rbf
    __shared__ float s_pref[64];
    __shared__ float s_k2[64];      // log2(e) * (-0.5/w^2)
    __shared__ float s_off[64];
    __shared__ float s_phi[2 * KS + 1];

    const float LOG2E = 1.4426950408889634f;
    int pv    = blockIdx.x / SLICES;       // (b,v) index
    int slice = blockIdx.x % SLICES;
    int b     = pv / MAXZ;
    int v     = pv % MAXZ;
    int tid   = threadIdx.x;

    if (tid < A) {
        float tw = t_wid[tid];
        float dt = t[b] - t_off[tid];
        float c  = (-0.5f / (tw * tw)) * LOG2E;
        sx[tid] = emb[(size_t)v * A + tid] * ex2f_fast(c * dt * dt);
    }
    if (tid < R) {
        float w = r_wid[tid];
        s_k2[tid]  = (-0.5f / (w * w)) * LOG2E;
        s_off[tid] = r_off[tid];
    }
    __syncthreads();
    if (tid < R) {
        float s = 0.0f;
        for (int a = 0; a < A; a++)
            s = fmaf(sx[a], W[(size_t)a * R + tid], s);
        s_pref[tid] = s;
    }
    __syncthreads();

    const float hh = DMAXF / (float)KNOTS;
    int base = slice * KS;
    for (int p = tid; p < 2 * KS + 1; p += blockDim.x) {
        float d = (float)(base * 2 + p) * (0.5f * hh);
        float acc = 0.0f;
        for (int r = 0; r < R; r++) {
            float dd = d - s_off[r];
            acc = fmaf(s_pref[r], ex2f_fast(s_k2[r] * dd * dd), acc);
        }
        s_phi[p] = acc;
    }
    __syncthreads();

    if (tid < KS) {
        float y0 = s_phi[2 * tid + 0];
        float ym = s_phi[2 * tid + 1];
        float y1 = s_phi[2 * tid + 2];
        float ca = y0;
        float cb = (4.0f * ym - 3.0f * y0 - y1) / hh;
        float cc = 2.0f * (y1 - 2.0f * ym + y0) / (hh * hh);
        g_table[(size_t)pv * KNOTS + base + tid] = make_float4(ca, cb, cc, 0.0f);
    }
}

// ---------------------------------------------------------------------------
// Kernel 2: main pairwise kernel. One block of 128 threads per (b, i).
// smem: [KNOTS] float4 table for (b, z[i]) + [3N] raw positions of batch b.
// Per pair: d -> table interval -> quadratic eval -> accumulate phi * r_ij.
// Diagonal j==i contributes exactly 0 (r_ij = 0 vector).
// ---------------------------------------------------------------------------
__global__ __launch_bounds__(128)
void vf_main_kernel(const float* __restrict__ pos,
                    const int*   __restrict__ z,
                    float*       __restrict__ out,
                    int N, int MAXZ) {
    extern __shared__ float4 smem4[];
    float4* s_tab = smem4;                       // [KNOTS]
    float*  s_pos = (float*)(smem4 + KNOTS);     // [3N]
    __shared__ float s_red[12];

    int bi  = blockIdx.x;
    int b   = bi / N;
    int i   = bi % N;
    int tid = threadIdx.x;

    const float* posb = pos + (size_t)b * N * 3;
    for (int idx = tid; idx < 3 * N; idx += 128)
        s_pos[idx] = posb[idx];

    int zi = z[i];
    const float4* tab = g_table + (size_t)(b * MAXZ + zi) * KNOTS;
    for (int idx = tid; idx < KNOTS; idx += 128)
        s_tab[idx] = tab[idx];
    __syncthreads();

    float pix = s_pos[3 * i + 0];
    float piy = s_pos[3 * i + 1];
    float piz = s_pos[3 * i + 2];

    const float inv_h = (float)KNOTS / DMAXF;
    const float hh    = DMAXF / (float)KNOTS;

    float a0 = 0.0f, a1 = 0.0f, a2 = 0.0f;
    for (int j = tid; j < N; j += 128) {
        float rx = pix - s_pos[3 * j + 0];
        float ry = piy - s_pos[3 * j + 1];
        float rz = piz - s_pos[3 * j + 2];
        float d2 = fmaf(rx, rx, fmaf(ry, ry, rz * rz)) + 1e-6f;
        float d  = sqrtf_fast(d2);
        int   k  = (int)(d * inv_h);
        k = (k < KNOTS - 1) ? k : (KNOTS - 1);
        float u  = fmaf(-(float)k, hh, d);
        float4 c = s_tab[k];
        float phi = fmaf(fmaf(c.z, u, c.y), u, c.x);
        a0 = fmaf(phi, rx, a0);
        a1 = fmaf(phi, ry, a1);
        a2 = fmaf(phi, rz, a2);
    }

    // 4-warp reduction
#pragma unroll
    for (int off = 16; off > 0; off >>= 1) {
        a0 += __shfl_down_sync(0xFFFFFFFFu, a0, off);
        a1 += __shfl_down_sync(0xFFFFFFFFu, a1, off);
        a2 += __shfl_down_sync(0xFFFFFFFFu, a2, off);
    }
    int warp = tid >> 5;
    int lane = tid & 31;
    if (lane == 0) {
        s_red[warp * 3 + 0] = a0;
        s_red[warp * 3 + 1] = a1;
        s_red[warp * 3 + 2] = a2;
    }
    __syncthreads();
    if (tid == 0) {
        float s0 = 0.0f, s1 = 0.0f, s2 = 0.0f;
#pragma unroll
        for (int w = 0; w < 4; w++) {
            s0 += s_red[w * 3 + 0];
            s1 += s_red[w * 3 + 1];
            s2 += s_red[w * 3 + 2];
        }
        out[(size_t)bi * 3 + 0] = s0 + pix;
        out[(size_t)bi * 3 + 1] = s1 + piy;
        out[(size_t)bi * 3 + 2] = s2 + piz;
    }
}

// ---------------------------------------------------------------------------
// Inputs (metadata order):
//  0 positions [B,N,3] f32, 1 t [B] f32, 2 z [N] i32, 3 emb [MAXZ,A] f32,
//  4 W [A,R] f32, 5 rad_off [R], 6 rad_wid [R], 7 time_off [A], 8 time_wid [A]
// ---------------------------------------------------------------------------
extern "C" void kernel_launch(void* const* d_in, const int* in_sizes, int n_in,
                              void* d_out, int out_size) {
    const float* positions = (const float*)d_in[0];
    const float* t         = (const float*)d_in[1];
    const int*   z         = (const int*)  d_in[2];
    const float* emb       = (const float*)d_in[3];
    const float* W         = (const float*)d_in[4];
    const float* r_off     = (const float*)d_in[5];
    const float* r_wid     = (const float*)d_in[6];
    const float* t_off     = (const float*)d_in[7];
    const float* t_wid     = (const float*)d_in[8];

    int B    = in_sizes[1];
    int N    = in_sizes[2];
    int R    = in_sizes[5];
    int A    = in_sizes[7];
    int MAXZ = in_sizes[3] / A;

    build_table_kernel<<<B * MAXZ * SLICES, 256>>>(
        t, emb, W, r_off, r_wid, t_off, t_wid, A, R, MAXZ);

    size_t smem = (size_t)KNOTS * sizeof(float4) + (size_t)3 * N * sizeof(float);
    vf_main_kernel<<<B * N, 128, smem>>>(positions, z, (float*)d_out, N, MAXZ);
}

// round 3
// speedup vs baseline: 2.4176x; 1.0664x over previous
#include <cuda_runtime.h>
#include <cuda_bf16.h>

// ---------------------------------------------------------------------------
// phi_{b,v}(d) = sum_r pref_r[b,v] * exp(-0.5/w_r^2 * (d - o_r)^2)
// tabulated as piecewise quadratics: KNOTS intervals over d in [0, DMAX].
// ---------------------------------------------------------------------------
#define KNOTS   512
#define DMAXF   16.0f
#define SLICES  4
#define KS      (KNOTS / SLICES)   // 128 intervals per build block

__device__ float  g_pref[2 * 128 * 64];            // [B*MAXZ, R]
__device__ float4 g_table[2 * 128 * KNOTS];        // [B*MAXZ, KNOTS]

__device__ __forceinline__ float ex2f_fast(float x) {
    float y; asm("ex2.approx.ftz.f32 %0, %1;" : "=f"(y) : "f"(x)); return y;
}
__device__ __forceinline__ float sqrtf_fast(float x) {
    float y; asm("sqrt.approx.f32 %0, %1;" : "=f"(y) : "f"(x)); return y;
}

// ---------------------------------------------------------------------------
// Kernel 1: prefactors. grid = B*MAXZ blocks, 128 threads.
//   pref[b,v,r] = sum_a emb[v,a]*exp(-0.5/tw_a^2 (t_b-to_a)^2) * W[a,r]
// W staged in smem once; accumulation unrolled for MLP.
// ---------------------------------------------------------------------------
__global__ __launch_bounds__(128)
void prep_pref_kernel(const float* __restrict__ t,
                      const float* __restrict__ emb,
                      const float* __restrict__ W,
                      const float* __restrict__ t_off,
                      const float* __restrict__ t_wid,
                      int A, int R, int MAXZ) {
    __shared__ float sW[4096];      // A*R <= 4096
    __shared__ float sx[128];
    const float LOG2E = 1.4426950408889634f;
    int b = blockIdx.x / MAXZ;
    int v = blockIdx.x % MAXZ;
    int tid = threadIdx.x;

    int AR = A * R;
    for (int idx = tid; idx < AR; idx += 128) sW[idx] = W[idx];
    if (tid < A) {
        float tw = t_wid[tid];
        float dt = t[b] - t_off[tid];
        float c  = (-0.5f / (tw * tw)) * LOG2E;
        sx[tid] = emb[(size_t)v * A + tid] * ex2f_fast(c * dt * dt);
    }
    __syncthreads();
    if (tid < R) {
        float s0 = 0.f, s1 = 0.f, s2 = 0.f, s3 = 0.f;
        int a = 0;
        for (; a + 3 < A; a += 4) {
            s0 = fmaf(sx[a + 0], sW[(a + 0) * R + tid], s0);
            s1 = fmaf(sx[a + 1], sW[(a + 1) * R + tid], s1);
            s2 = fmaf(sx[a + 2], sW[(a + 2) * R + tid], s2);
            s3 = fmaf(sx[a + 3], sW[(a + 3) * R + tid], s3);
        }
        for (; a < A; a++) s0 = fmaf(sx[a], sW[a * R + tid], s0);
        g_pref[(size_t)blockIdx.x * R + tid] = (s0 + s1) + (s2 + s3);
    }
}

// ---------------------------------------------------------------------------
// Kernel 2: build tables. grid = (B*MAXZ)*SLICES blocks, 256 threads.
// Sample phi at 2*KS+1 points of the slice, fit quadratic per interval.
// ---------------------------------------------------------------------------
template <int RR>
__global__ __launch_bounds__(256)
void build_table_kernel(const float* __restrict__ r_off,
                        const float* __restrict__ r_wid,
                        int R) {
    __shared__ float s_pref[64], s_k2[64], s_off[64];
    __shared__ float s_phi[2 * KS + 1];
    const float LOG2E = 1.4426950408889634f;
    int pv    = blockIdx.x / SLICES;
    int slice = blockIdx.x % SLICES;
    int tid   = threadIdx.x;
    int Ruse  = (RR > 0) ? RR : R;

    if (tid < Ruse) {
        float w = r_wid[tid];
        s_k2[tid]   = (-0.5f / (w * w)) * LOG2E;
        s_off[tid]  = r_off[tid];
        s_pref[tid] = g_pref[(size_t)pv * R + tid];
    }
    __syncthreads();

    const float hh = DMAXF / (float)KNOTS;
    int base = slice * KS;
    for (int p = tid; p < 2 * KS + 1; p += 256) {
        float d = (float)(base * 2 + p) * (0.5f * hh);
        float acc = 0.0f;
        if (RR > 0) {
#pragma unroll
            for (int r = 0; r < RR; r++) {
                float dd = d - s_off[r];
                acc = fmaf(s_pref[r], ex2f_fast(s_k2[r] * dd * dd), acc);
            }
        } else {
            for (int r = 0; r < R; r++) {
                float dd = d - s_off[r];
                acc = fmaf(s_pref[r], ex2f_fast(s_k2[r] * dd * dd), acc);
            }
        }
        s_phi[p] = acc;
    }
    __syncthreads();

    if (tid < KS) {
        float y0 = s_phi[2 * tid + 0];
        float ym = s_phi[2 * tid + 1];
        float y1 = s_phi[2 * tid + 2];
        float inv_h = 1.0f / hh;
        float ca = y0;
        float cb = (4.0f * ym - 3.0f * y0 - y1) * inv_h;
        float cc = 2.0f * (y1 - 2.0f * ym + y0) * (inv_h * inv_h);
        g_table[(size_t)pv * KNOTS + base + tid] = make_float4(ca, cb, cc, 0.0f);
    }
}

// ---------------------------------------------------------------------------
// Kernel 3: main pairwise kernel. 128 threads; each block handles TWO rows
// (i0, i0 + ceil(N/2)) of one batch, sharing the staged positions. Table
// lookups via __ldg (L1-resident 8KB working set per row). Single wave.
// ---------------------------------------------------------------------------
__global__ __launch_bounds__(128)
void vf_main_kernel(const float* __restrict__ pos,
                    const int*   __restrict__ z,
                    float*       __restrict__ out,
                    int N, int MAXZ) {
    extern __shared__ float4 s_pos[];   // [N]
    __shared__ float s_red[24];

    int halfN = (N + 1) >> 1;
    int b  = blockIdx.x / halfN;
    int i0 = blockIdx.x % halfN;
    int i1 = i0 + halfN;
    bool has1 = (i1 < N);
    int tid = threadIdx.x;

    const float* posb = pos + (size_t)b * N * 3;
    for (int idx = tid; idx < N; idx += 128)
        s_pos[idx] = make_float4(posb[idx * 3 + 0], posb[idx * 3 + 1],
                                 posb[idx * 3 + 2], 0.0f);

    const float4* tab0 = g_table + (size_t)(b * MAXZ + z[i0]) * KNOTS;
    const float4* tab1 = has1 ? (g_table + (size_t)(b * MAXZ + z[i1]) * KNOTS)
                              : tab0;
    __syncthreads();

    float4 p0 = s_pos[i0];
    float4 p1 = has1 ? s_pos[i1] : p0;

    const float inv_h = (float)KNOTS / DMAXF;
    const float hh    = DMAXF / (float)KNOTS;
    const float dclamp = DMAXF - 0.5f * hh;

    float a00 = 0.f, a01 = 0.f, a02 = 0.f;
    float a10 = 0.f, a11 = 0.f, a12 = 0.f;

#pragma unroll 4
    for (int j = tid; j < N; j += 128) {
        float4 pj = s_pos[j];
        // row i0
        {
            float rx = p0.x - pj.x, ry = p0.y - pj.y, rz = p0.z - pj.z;
            float d2 = fmaf(rx, rx, fmaf(ry, ry, rz * rz)) + 1e-6f;
            float d  = sqrtf_fast(d2);
            float dc = fminf(d, dclamp);
            int   k  = (int)(dc * inv_h);
            float u  = fmaf(-(float)k, hh, dc);
            float4 c = __ldg(&tab0[k]);
            float phi = fmaf(fmaf(c.z, u, c.y), u, c.x);
            a00 = fmaf(phi, rx, a00);
            a01 = fmaf(phi, ry, a01);
            a02 = fmaf(phi, rz, a02);
        }
        // row i1
        {
            float rx = p1.x - pj.x, ry = p1.y - pj.y, rz = p1.z - pj.z;
            float d2 = fmaf(rx, rx, fmaf(ry, ry, rz * rz)) + 1e-6f;
            float d  = sqrtf_fast(d2);
            float dc = fminf(d, dclamp);
            int   k  = (int)(dc * inv_h);
            float u  = fmaf(-(float)k, hh, dc);
            float4 c = __ldg(&tab1[k]);
            float phi = fmaf(fmaf(c.z, u, c.y), u, c.x);
            a10 = fmaf(phi, rx, a10);
            a11 = fmaf(phi, ry, a11);
            a12 = fmaf(phi, rz, a12);
        }
    }

    // reduce 6 accumulators across 4 warps
#pragma unroll
    for (int off = 16; off > 0; off >>= 1) {
        a00 += __shfl_down_sync(0xFFFFFFFFu, a00, off);
        a01 += __shfl_down_sync(0xFFFFFFFFu, a01, off);
        a02 += __shfl_down_sync(0xFFFFFFFFu, a02, off);
        a10 += __shfl_down_sync(0xFFFFFFFFu, a10, off);
        a11 += __shfl_down_sync(0xFFFFFFFFu, a11, off);
        a12 += __shfl_down_sync(0xFFFFFFFFu, a12, off);
    }
    int warp = tid >> 5, lane = tid & 31;
    if (lane == 0) {
        s_red[warp * 6 + 0] = a00; s_red[warp * 6 + 1] = a01;
        s_red[warp * 6 + 2] = a02; s_red[warp * 6 + 3] = a10;
        s_red[warp * 6 + 4] = a11; s_red[warp * 6 + 5] = a12;
    }
    __syncthreads();
    if (tid == 0) {
        float r0 = 0.f, r1 = 0.f, r2 = 0.f, r3 = 0.f, r4 = 0.f, r5 = 0.f;
#pragma unroll
        for (int w = 0; w < 4; w++) {
            r0 += s_red[w * 6 + 0]; r1 += s_red[w * 6 + 1];
            r2 += s_red[w * 6 + 2]; r3 += s_red[w * 6 + 3];
            r4 += s_red[w * 6 + 4]; r5 += s_red[w * 6 + 5];
        }
        size_t o0 = ((size_t)b * N + i0) * 3;
        out[o0 + 0] = r0 + p0.x;
        out[o0 + 1] = r1 + p0.y;
        out[o0 + 2] = r2 + p0.z;
        if (has1) {
            size_t o1 = ((size_t)b * N + i1) * 3;
            out[o1 + 0] = r3 + p1.x;
            out[o1 + 1] = r4 + p1.y;
            out[o1 + 2] = r5 + p1.z;
        }
    }
}

// ---------------------------------------------------------------------------
// Inputs (metadata order):
//  0 positions [B,N,3] f32, 1 t [B] f32, 2 z [N] i32, 3 emb [MAXZ,A] f32,
//  4 W [A,R] f32, 5 rad_off [R], 6 rad_wid [R], 7 time_off [A], 8 time_wid [A]
// ---------------------------------------------------------------------------
extern "C" void kernel_launch(void* const* d_in, const int* in_sizes, int n_in,
                              void* d_out, int out_size) {
    const float* positions = (const float*)d_in[0];
    const float* t         = (const float*)d_in[1];
    const int*   z         = (const int*)  d_in[2];
    const float* emb       = (const float*)d_in[3];
    const float* W         = (const float*)d_in[4];
    const float* r_off     = (const float*)d_in[5];
    const float* r_wid     = (const float*)d_in[6];
    const float* t_off     = (const float*)d_in[7];
    const float* t_wid     = (const float*)d_in[8];

    int B    = in_sizes[1];
    int N    = in_sizes[2];
    int R    = in_sizes[5];
    int A    = in_sizes[7];
    int MAXZ = in_sizes[3] / A;

    prep_pref_kernel<<<B * MAXZ, 128>>>(t, emb, W, t_off, t_wid, A, R, MAXZ);

    if (R == 50)
        build_table_kernel<50><<<B * MAXZ * SLICES, 256>>>(r_off, r_wid, R);
    else
        build_table_kernel<0><<<B * MAXZ * SLICES, 256>>>(r_off, r_wid, R);

    int halfN = (N + 1) >> 1;
    size_t smem = (size_t)N * sizeof(float4);
    vf_main_kernel<<<B * halfN, 128, smem>>>(positions, z, (float*)d_out,
                                             N, MAXZ);
}